// round 2
// baseline (speedup 1.0000x reference)
#include <cuda_runtime.h>
#include <math.h>

#define NKK 20
#define DD 128
#define NT 256
#define HIDN 512

// shared-memory layout (floats)
#define OFF_A 0       // 2560: edge_feat tile -> scores(1600) + scratch
#define OFF_Z 2560    // 2560: z (message), later ffn output / x2
#define OFF_Q 5120    // 2560
#define OFF_KT 7680   // 2560: K transposed [128][20]
#define OFF_V 10240   // 2560
#define OFF_O 12800   // 2560: attention output
#define OFF_X 15360   // 2560: post-attn LN activations
#define OFF_H1 5120   // 10240: FFN hidden overlays Q/KT/V/O
#define SMEM_FLOATS 17920
#define SMEM_BYTES (SMEM_FLOATS * 4)

__device__ __forceinline__ float gelu_exact(float x) {
    return 0.5f * x * (1.0f + erff(x * 0.7071067811865475f));
}

// C[20][128] = A[20][KD] @ W[KD][128-col-slice], A in smem, W in global (L2-hot).
// Thread = (colgroup of 4 via float4, rowgroup of up to 3 strided rows).
template<int KD, bool TRANSPOSE_C>
__device__ __forceinline__ void gemm20(const float* Asm, int lda,
                                       const float* __restrict__ W, int ldw,
                                       float* Csm, int ldc, int tid)
{
    const int cg = tid & 31;       // 32 col groups
    const int rg = tid >> 5;       // 8 row groups
    const int d0 = cg << 2;
    float acc[3][4];
#pragma unroll
    for (int i = 0; i < 3; i++) { acc[i][0] = 0.f; acc[i][1] = 0.f; acc[i][2] = 0.f; acc[i][3] = 0.f; }
#pragma unroll 4
    for (int e = 0; e < KD; e += 4) {
        const float* wp = W + (size_t)e * ldw + d0;
        float4 w0 = *(const float4*)(wp);
        float4 w1 = *(const float4*)(wp + ldw);
        float4 w2 = *(const float4*)(wp + 2 * ldw);
        float4 w3 = *(const float4*)(wp + 3 * ldw);
#pragma unroll
        for (int i = 0; i < 3; i++) {
            int r = rg + (i << 3);
            if (r < NKK) {
                float4 a = *(const float4*)(Asm + r * lda + e);
                acc[i][0] += a.x * w0.x; acc[i][0] += a.y * w1.x; acc[i][0] += a.z * w2.x; acc[i][0] += a.w * w3.x;
                acc[i][1] += a.x * w0.y; acc[i][1] += a.y * w1.y; acc[i][1] += a.z * w2.y; acc[i][1] += a.w * w3.y;
                acc[i][2] += a.x * w0.z; acc[i][2] += a.y * w1.z; acc[i][2] += a.z * w2.z; acc[i][2] += a.w * w3.z;
                acc[i][3] += a.x * w0.w; acc[i][3] += a.y * w1.w; acc[i][3] += a.z * w2.w; acc[i][3] += a.w * w3.w;
            }
        }
    }
#pragma unroll
    for (int i = 0; i < 3; i++) {
        int r = rg + (i << 3);
        if (r < NKK) {
            if (TRANSPOSE_C) {
#pragma unroll
                for (int c = 0; c < 4; c++) Csm[(d0 + c) * ldc + r] = acc[i][c];
            } else {
                float4 v4; v4.x = acc[i][0]; v4.y = acc[i][1]; v4.z = acc[i][2]; v4.w = acc[i][3];
                *(float4*)(Csm + r * ldc + d0) = v4;
            }
        }
    }
}

// Row-wise LayerNorm over [20][128] in smem, in place. Bank-rotated stats reads.
__device__ __forceinline__ void ln_rows(float* rows, const float* __restrict__ g,
                                        const float* __restrict__ b, float* scratch, int tid)
{
    if (tid < NKK) {
        float m = 0.f;
#pragma unroll 8
        for (int dd = 0; dd < DD; dd++) m += rows[tid * DD + ((dd + tid) & 127)];
        m *= (1.0f / DD);
        float v = 0.f;
#pragma unroll 8
        for (int dd = 0; dd < DD; dd++) { float x = rows[tid * DD + ((dd + tid) & 127)] - m; v += x * x; }
        v *= (1.0f / DD);
        scratch[tid] = m;
        scratch[NKK + tid] = rsqrtf(v + 1e-5f);
    }
    __syncthreads();
    for (int i = tid; i < NKK * DD; i += NT) {
        int r = i >> 7, d = i & 127;
        rows[i] = (rows[i] - scratch[r]) * scratch[NKK + r] * g[d] + b[d];
    }
    __syncthreads();
}

__global__ __launch_bounds__(NT)
void tgat_kernel(const float* __restrict__ nh, const float* __restrict__ t,
                 const float* __restrict__ t_now, const float* __restrict__ ef,
                 const float* __restrict__ bfreq, const float* __restrict__ phase,
                 const float* __restrict__ e_w, const float* __restrict__ e_b,
                 const float* __restrict__ wq, const float* __restrict__ wk,
                 const float* __restrict__ wv, const float* __restrict__ wq_src,
                 const float* __restrict__ afc_w, const float* __restrict__ afc_b,
                 const float* __restrict__ aln_g, const float* __restrict__ aln_b,
                 const float* __restrict__ f_w1, const float* __restrict__ f_b1,
                 const float* __restrict__ f_w2, const float* __restrict__ f_b2,
                 const float* __restrict__ fln_g, const float* __restrict__ fln_b,
                 const float* __restrict__ f2n_w, const float* __restrict__ f2n_b,
                 const float* __restrict__ oln_g, const float* __restrict__ oln_b,
                 float* __restrict__ out)
{
    extern __shared__ float sm[];
    const int n = blockIdx.x;
    const int tid = threadIdx.x;
    const size_t base = (size_t)n * (NKK * DD);

    // ---- message: z = node_h_src + gelu(edge_feat @ We + be) + time_enc ----
    for (int i = tid; i < NKK * DD; i += NT) sm[OFF_A + i] = ef[base + i];
    __syncthreads();
    gemm20<128, false>(sm + OFF_A, DD, e_w, DD, sm + OFF_Z, DD, tid);
    __syncthreads();
    const float tn = t_now[0];
    for (int i = tid; i < NKK * DD; i += NT) {
        int k = i >> 7, d = i & 127;
        float g = gelu_exact(sm[OFF_Z + i] + e_b[d]);
        float te = cosf((tn - t[n * NKK + k]) * bfreq[d] + phase[d]);
        sm[OFF_Z + i] = nh[base + i] + g + te;
    }
    __syncthreads();

    // ---- q,k,v projections (K stored transposed) ----
    gemm20<128, false>(sm + OFF_Z, DD, wq, DD, sm + OFF_Q, DD, tid);
    gemm20<128, true >(sm + OFF_Z, DD, wk, DD, sm + OFF_KT, NKK, tid);
    gemm20<128, false>(sm + OFF_Z, DD, wv, DD, sm + OFF_V, DD, tid);
    __syncthreads();

    // self message: self_q replaces last slot of q, k AND v (faithful to ref)
    if (tid < DD) {
        float a = 0.f;
        const float* z19 = sm + OFF_Z + 19 * DD;
#pragma unroll 4
        for (int e = 0; e < DD; e++) a += z19[e] * wq_src[e * DD + tid];
        sm[OFF_Q + 19 * DD + tid] = a;
        sm[OFF_V + 19 * DD + tid] = a;
        sm[OFF_KT + tid * NKK + 19] = a;
    }
    __syncthreads();

    // ---- attention scores: [4 heads][20 q][20 k] ----
    for (int idx = tid; idx < 1600; idx += NT) {
        int h = idx / 400, rem = idx % 400;
        int qi = rem / 20, ki = rem % 20;
        const float* qp = sm + OFF_Q + qi * DD + h * 32;
        const float* kp = sm + OFF_KT + (h * 32) * NKK + ki;
        float s = 0.f;
#pragma unroll
        for (int j = 0; j < 32; j++) s += qp[j] * kp[j * NKK];
        sm[OFF_A + idx] = s * 0.17677669529663687f; // 1/sqrt(32)
    }
    __syncthreads();

    // softmax over k (80 rows of 20)
    if (tid < 80) {
        float* row = sm + OFF_A + tid * 20;
        float m = row[0];
#pragma unroll
        for (int j = 1; j < 20; j++) m = fmaxf(m, row[j]);
        float s = 0.f;
#pragma unroll
        for (int j = 0; j < 20; j++) { float e2 = expf(row[j] - m); row[j] = e2; s += e2; }
        float inv = 1.f / s;
#pragma unroll
        for (int j = 0; j < 20; j++) row[j] *= inv;
    }
    __syncthreads();

    // attention output: O[q][h*32+d] = sum_k P[h][q][k] * V[k][h*32+d]
    for (int i = tid; i < NKK * DD; i += NT) {
        int q = i >> 7, d = i & 127, h = d >> 5;
        const float* pp = sm + OFF_A + (h * 20 + q) * 20;
        const float* vp = sm + OFF_V + d;
        float s = 0.f;
#pragma unroll
        for (int ki = 0; ki < 20; ki++) s += pp[ki] * vp[ki * DD];
        sm[OFF_O + i] = s;
    }
    __syncthreads();

    // ---- attn_fc + residual(z) + LN ----
    gemm20<128, false>(sm + OFF_O, DD, afc_w, DD, sm + OFF_X, DD, tid);
    __syncthreads();
    for (int i = tid; i < NKK * DD; i += NT) {
        int d = i & 127;
        sm[OFF_X + i] = sm[OFF_X + i] + afc_b[d] + sm[OFF_Z + i];
    }
    __syncthreads();
    ln_rows(sm + OFF_X, aln_g, aln_b, sm + OFF_A, tid);

    // ---- FFN: relu(x@W1+b1)@W2+b2 + residual + LN ----
    for (int c = 0; c < 4; c++)
        gemm20<128, false>(sm + OFF_X, DD, f_w1 + c * DD, HIDN, sm + OFF_H1 + c * DD, HIDN, tid);
    __syncthreads();
    for (int i = tid; i < NKK * HIDN; i += NT) {
        float v = sm[OFF_H1 + i] + f_b1[i & 511];
        sm[OFF_H1 + i] = v > 0.f ? v : 0.f;
    }
    __syncthreads();
    gemm20<512, false>(sm + OFF_H1, HIDN, f_w2, DD, sm + OFF_Z, DD, tid);
    __syncthreads();
    for (int i = tid; i < NKK * DD; i += NT) {
        int d = i & 127;
        sm[OFF_Z + i] = sm[OFF_Z + i] + f_b2[d] + sm[OFF_X + i];
    }
    __syncthreads();
    ln_rows(sm + OFF_Z, fln_g, fln_b, sm + OFF_A, tid);

    // ---- fuse self slot + neighborhood mean -> fea2node -> out LN ----
    if (tid < DD) {
        float s = 0.f;
#pragma unroll
        for (int k = 0; k < 19; k++) s += sm[OFF_Z + k * DD + tid];
        sm[OFF_A + 64 + DD + tid] = s * (1.0f / 19.0f);  // neighborhood
        sm[OFF_A + 64 + tid] = sm[OFF_Z + 19 * DD + tid]; // self slot
    }
    __syncthreads();
    if (tid < DD) {
        float a = 0.f;
        const float* fu = sm + OFF_A + 64;
#pragma unroll 4
        for (int e = 0; e < 2 * DD; e++) a += fu[e] * f2n_w[e * DD + tid];
        float y = gelu_exact(a + f2n_b[tid]) + nh[base + 19 * DD + tid];
        sm[OFF_A + 400 + tid] = y;
    }
    __syncthreads();
    if (tid == 0) {
        float m = 0.f;
        for (int d = 0; d < DD; d++) m += sm[OFF_A + 400 + d];
        m *= (1.0f / DD);
        float v = 0.f;
        for (int d = 0; d < DD; d++) { float x = sm[OFF_A + 400 + d] - m; v += x * x; }
        v *= (1.0f / DD);
        sm[OFF_A + 560] = m;
        sm[OFF_A + 561] = rsqrtf(v + 1e-5f);
    }
    __syncthreads();
    if (tid < DD) {
        float y = (sm[OFF_A + 400 + tid] - sm[OFF_A + 560]) * sm[OFF_A + 561];
        out[(size_t)n * DD + tid] = y * oln_g[tid] + oln_b[tid];
    }
}

extern "C" void kernel_launch(void* const* d_in, const int* in_sizes, int n_in,
                              void* d_out, int out_size) {
    (void)n_in; (void)out_size;
    const float* nh      = (const float*)d_in[0];   // node_h_src [N,20,128]
    const float* t       = (const float*)d_in[1];   // t [N,20]
    const float* t_now   = (const float*)d_in[2];   // t_now [1]
    const float* ef      = (const float*)d_in[3];   // edge_feat [N,20,128]
    const float* bfreq   = (const float*)d_in[4];   // basis_freq [128]
    const float* phase   = (const float*)d_in[5];   // phase [128]
    const float* e_w     = (const float*)d_in[6];   // edge_fc_w [128,128]
    const float* e_b     = (const float*)d_in[7];   // edge_fc_b [128]
    const float* wq      = (const float*)d_in[8];   // w_qs [128,128]
    const float* wk      = (const float*)d_in[9];   // w_ks [128,128]
    const float* wv      = (const float*)d_in[10];  // w_vs [128,128]
    const float* wq_src  = (const float*)d_in[11];  // w_qs_src [128,128]
    const float* afc_w   = (const float*)d_in[12];  // attn_fc_w [128,128]
    const float* afc_b   = (const float*)d_in[13];  // attn_fc_b [128]
    const float* aln_g   = (const float*)d_in[14];  // attn_ln_g [128]
    const float* aln_b   = (const float*)d_in[15];  // attn_ln_b [128]
    const float* f_w1    = (const float*)d_in[16];  // ffn_w1 [128,512]
    const float* f_b1    = (const float*)d_in[17];  // ffn_b1 [512]
    const float* f_w2    = (const float*)d_in[18];  // ffn_w2 [512,128]
    const float* f_b2    = (const float*)d_in[19];  // ffn_b2 [128]
    const float* fln_g   = (const float*)d_in[20];  // ffn_ln_g [128]
    const float* fln_b   = (const float*)d_in[21];  // ffn_ln_b [128]
    const float* f2n_w   = (const float*)d_in[22];  // fea2node_w [256,128]
    const float* f2n_b   = (const float*)d_in[23];  // fea2node_b [128]
    const float* oln_g   = (const float*)d_in[24];  // out_ln_g [128]
    const float* oln_b   = (const float*)d_in[25];  // out_ln_b [128]
    float* out = (float*)d_out;

    const int N = in_sizes[0] / (NKK * DD);

    cudaFuncSetAttribute(tgat_kernel, cudaFuncAttributeMaxDynamicSharedMemorySize, SMEM_BYTES);
    tgat_kernel<<<N, NT, SMEM_BYTES>>>(nh, t, t_now, ef, bfreq, phase, e_w, e_b,
                                       wq, wk, wv, wq_src, afc_w, afc_b, aln_g, aln_b,
                                       f_w1, f_b1, f_w2, f_b2, fln_g, fln_b,
                                       f2n_w, f2n_b, oln_g, oln_b, out);
}

// round 4
// speedup vs baseline: 1.1337x; 1.1337x over previous
#include <cuda_runtime.h>
#include <math.h>

#define NB 3
#define RROWS 60              // NB * 20
#define RPAD 64               // M padded for mma (4 tiles of 16)
#define LDA 132               // activation smem stride (bank-conflict-free A frags)
#define LDW 136               // weight-stage smem stride (bank-conflict-free B frags)
#define NT 256

// smem layout (floats)
#define OFF_Z   0
#define OFF_SA  (OFF_Z  + RPAD * LDA)
#define OFF_SB  (OFF_SA + RPAD * LDA)
#define OFF_SC  (OFF_SB + RPAD * LDA)
#define OFF_W   (OFF_SC + RPAD * LDA)      // 3*32*LDW floats (generic gemm uses first 2)
#define OFF_S   (OFF_W  + 3 * 32 * LDW)    // scores: NB*1600
#define OFF_SCR (OFF_S  + NB * 1600)       // 384 scratch
#define SMEM_FLOATS (OFF_SCR + 384)
#define SMEM_BYTES (SMEM_FLOATS * 4)

__device__ __forceinline__ float gelu_exact(float x) {
    return 0.5f * x * (1.0f + erff(x * 0.7071067811865475f));
}

__device__ __forceinline__ float to_tf32(float x) {
    unsigned u;
    asm("cvt.rna.tf32.f32 %0, %1;" : "=r"(u) : "f"(x));
    return __uint_as_float(u);
}

__device__ __forceinline__ void mma_tf32(float d[4], const float a[4], const float b[2]) {
    asm volatile(
        "mma.sync.aligned.m16n8k8.row.col.f32.tf32.tf32.f32 "
        "{%0,%1,%2,%3}, {%4,%5,%6,%7}, {%8,%9}, {%0,%1,%2,%3};"
        : "+f"(d[0]), "+f"(d[1]), "+f"(d[2]), "+f"(d[3])
        : "r"(__float_as_uint(a[0])), "r"(__float_as_uint(a[1])),
          "r"(__float_as_uint(a[2])), "r"(__float_as_uint(a[3])),
          "r"(__float_as_uint(b[0])), "r"(__float_as_uint(b[1])));
}

// stage one 32-row k-chunk of W (128 cols starting at col0) into smem, tf32-rounded
__device__ __forceinline__ void stageW(float* dst, const float* __restrict__ W,
                                       int ldw, int krow0, int col0, int tid) {
#pragma unroll
    for (int j = 0; j < 4; j++) {
        int idx = tid + j * NT;          // 0..1023
        int r = idx >> 5;                // 0..31
        int c4 = (idx & 31) << 2;        // 0..124
        float4 v = *(const float4*)(W + (size_t)(krow0 + r) * ldw + col0 + c4);
        float4 o;
        o.x = to_tf32(v.x); o.y = to_tf32(v.y); o.z = to_tf32(v.z); o.w = to_tf32(v.w);
        *(float4*)(dst + r * LDW + c4) = o;
    }
}

// acc[2][4][4] += sAct[64x128 (lda=LDA, tf32 values)] @ W[128][128 col-slice]
// double-buffered k-chunk staging through sWbuf (2 x 32 x LDW floats).
// Caller must have all threads synced before entry.
__device__ __forceinline__ void gemm128(float acc[2][4][4], const float* sAct,
                                        const float* __restrict__ Wg, int ldw, int col0,
                                        float* sWbuf, int tid) {
    const int lane = tid & 31, w = tid >> 5;
    const int mg = w & 1, ng = w >> 1;
    const int qr = lane >> 2, qc = lane & 3;
    stageW(sWbuf, Wg, ldw, 0, col0, tid);
    __syncthreads();
#pragma unroll
    for (int kc = 0; kc < 4; kc++) {
        const float* sw = sWbuf + (kc & 1) * (32 * LDW);
        if (kc < 3) stageW(sWbuf + ((kc + 1) & 1) * (32 * LDW), Wg, ldw, (kc + 1) * 32, col0, tid);
#pragma unroll
        for (int ks = 0; ks < 4; ks++) {
            const int k0 = kc * 32 + ks * 8;   // absolute k (A)
            const int kl = ks * 8;             // local k (staged W)
            float af[2][4];
#pragma unroll
            for (int mt = 0; mt < 2; mt++) {
                const float* ap = sAct + ((mg * 2 + mt) * 16 + qr) * LDA + k0 + qc;
                af[mt][0] = ap[0];
                af[mt][1] = ap[8 * LDA];
                af[mt][2] = ap[4];
                af[mt][3] = ap[8 * LDA + 4];
            }
#pragma unroll
            for (int nt = 0; nt < 4; nt++) {
                const float* bp = sw + (kl + qc) * LDW + (ng * 4 + nt) * 8 + qr;
                float bf[2];
                bf[0] = bp[0];
                bf[1] = bp[4 * LDW];
#pragma unroll
                for (int mt = 0; mt < 2; mt++) mma_tf32(acc[mt][nt], af[mt], bf);
            }
        }
        __syncthreads();
    }
}

#define ACC_ZERO(acc) do { _Pragma("unroll") for (int _m=0;_m<2;_m++) _Pragma("unroll") for (int _n=0;_n<4;_n++) { acc[_m][_n][0]=0.f;acc[_m][_n][1]=0.f;acc[_m][_n][2]=0.f;acc[_m][_n][3]=0.f; } } while(0)

// store acc tile set to dst (stride LDA); TF: 0 = raw, 1 = tf32-round
template<int TF>
__device__ __forceinline__ void store_acc(float* dst, float acc[2][4][4], int tid) {
    const int lane = tid & 31, w = tid >> 5;
    const int mg = w & 1, ng = w >> 1;
    const int qr = lane >> 2, qc = lane & 3;
#pragma unroll
    for (int mt = 0; mt < 2; mt++) {
        int r = (mg * 2 + mt) * 16 + qr;
#pragma unroll
        for (int nt = 0; nt < 4; nt++) {
            int c = (ng * 4 + nt) * 8 + qc * 2;
            float v0 = acc[mt][nt][0], v1 = acc[mt][nt][1];
            float v2 = acc[mt][nt][2], v3 = acc[mt][nt][3];
            if (TF) { v0 = to_tf32(v0); v1 = to_tf32(v1); v2 = to_tf32(v2); v3 = to_tf32(v3); }
            dst[r * LDA + c] = v0;
            dst[r * LDA + c + 1] = v1;
            dst[(r + 8) * LDA + c] = v2;
            dst[(r + 8) * LDA + c + 1] = v3;
        }
    }
}

// LayerNorm over RROWS rows of 128 (stride LDA), in place; TF controls output rounding
template<int TF>
__device__ __forceinline__ void ln_rows60(float* rows, const float* __restrict__ g,
                                          const float* __restrict__ b, float* scr, int tid) {
    if (tid < RROWS) {
        float m = 0.f;
#pragma unroll 8
        for (int dd = 0; dd < 128; dd++) m += rows[tid * LDA + ((dd + tid) & 127)];
        m *= (1.0f / 128.0f);
        float v = 0.f;
#pragma unroll 8
        for (int dd = 0; dd < 128; dd++) {
            float x = rows[tid * LDA + ((dd + tid) & 127)] - m;
            v += x * x;
        }
        v *= (1.0f / 128.0f);
        scr[tid] = m;
        scr[RROWS + tid] = rsqrtf(v + 1e-5f);
    }
    __syncthreads();
    for (int i = tid; i < RROWS * 128; i += NT) {
        int r = i >> 7, d = i & 127;
        float y = (rows[r * LDA + d] - scr[r]) * scr[RROWS + r] * g[d] + b[d];
        rows[r * LDA + d] = TF ? to_tf32(y) : y;
    }
    __syncthreads();
}

__global__ __launch_bounds__(NT, 1)
void tgat_kernel(const float* __restrict__ nh, const float* __restrict__ t,
                 const float* __restrict__ t_now, const float* __restrict__ ef,
                 const float* __restrict__ bfreq, const float* __restrict__ phase,
                 const float* __restrict__ e_w, const float* __restrict__ e_b,
                 const float* __restrict__ wq, const float* __restrict__ wk,
                 const float* __restrict__ wv, const float* __restrict__ wq_src,
                 const float* __restrict__ afc_w, const float* __restrict__ afc_b,
                 const float* __restrict__ aln_g, const float* __restrict__ aln_b,
                 const float* __restrict__ f_w1, const float* __restrict__ f_b1,
                 const float* __restrict__ f_w2, const float* __restrict__ f_b2,
                 const float* __restrict__ fln_g, const float* __restrict__ fln_b,
                 const float* __restrict__ f2n_w, const float* __restrict__ f2n_b,
                 const float* __restrict__ oln_g, const float* __restrict__ oln_b,
                 float* __restrict__ out, int Ntot)
{
    extern __shared__ float sm[];
    const int tid = threadIdx.x;
    const int n0 = blockIdx.x * NB;
    const int nodes_here = min(NB, Ntot - n0);

    float* sZ = sm + OFF_Z;
    float* sA = sm + OFF_SA;
    float* sB = sm + OFF_SB;
    float* sC = sm + OFF_SC;
    float* sW = sm + OFF_W;
    float* sS = sm + OFF_S;
    float* scr = sm + OFF_SCR;

    // ---- load edge_feat into sA (tf32), zero pad rows ----
    for (int i = tid; i < RROWS * 128; i += NT) {
        int r = i >> 7, d = i & 127;
        int node = r / 20, kk = r % 20;
        float v = (node < nodes_here) ? ef[(size_t)(n0 + node) * 2560 + kk * 128 + d] : 0.f;
        sA[r * LDA + d] = to_tf32(v);
    }
    for (int i = tid; i < (RPAD - RROWS) * LDA; i += NT) sA[RROWS * LDA + i] = 0.f;
    __syncthreads();

    float acc[2][4][4];

    // ---- E = ef @ e_w  -> sZ (raw) ----
    ACC_ZERO(acc);
    gemm128(acc, sA, e_w, 128, 0, sW, tid);
    store_acc<0>(sZ, acc, tid);
    __syncthreads();

    // ---- z = nh + gelu(E + e_b) + cos((tn - t)*freq + phase) -> sZ (tf32) ----
    const float tn = t_now[0];
    for (int i = tid; i < RROWS * 128; i += NT) {
        int r = i >> 7, d = i & 127;
        int node = r / 20, kk = r % 20;
        float z;
        if (node < nodes_here) {
            float g = gelu_exact(sZ[r * LDA + d] + e_b[d]);
            float te = cosf((tn - t[(n0 + node) * 20 + kk]) * bfreq[d] + phase[d]);
            z = nh[(size_t)(n0 + node) * 2560 + kk * 128 + d] + g + te;
        } else z = 0.f;
        sZ[r * LDA + d] = to_tf32(z);
    }
    __syncthreads();

    // ---- Q -> sA, K -> sB, V -> sC ----
    ACC_ZERO(acc); gemm128(acc, sZ, wq, 128, 0, sW, tid); store_acc<1>(sA, acc, tid); __syncthreads();
    ACC_ZERO(acc); gemm128(acc, sZ, wk, 128, 0, sW, tid); store_acc<1>(sB, acc, tid); __syncthreads();
    ACC_ZERO(acc); gemm128(acc, sZ, wv, 128, 0, sW, tid); store_acc<1>(sC, acc, tid); __syncthreads();

    // ---- self_q replaces last slot of Q, K, V ----
    for (int idx = tid; idx < NB * 128; idx += NT) {
        int node = idx >> 7, d = idx & 127;
        const float* zr = sZ + (node * 20 + 19) * LDA;
        float a = 0.f;
#pragma unroll 4
        for (int e = 0; e < 128; e++) a += zr[e] * wq_src[e * 128 + d];
        float v = to_tf32(a);
        int row = node * 20 + 19;
        sA[row * LDA + d] = v;
        sB[row * LDA + d] = v;
        sC[row * LDA + d] = v;
    }
    __syncthreads();

    // ---- scores [node][h][q][k] ----
    for (int idx = tid; idx < NB * 1600; idx += NT) {
        int node = idx / 1600, rem = idx % 1600;
        int h = rem / 400, qi = (rem / 20) % 20, ki = rem % 20;
        const float* qp = sA + (node * 20 + qi) * LDA + h * 32;
        const float* kp = sB + (node * 20 + ki) * LDA + h * 32;
        float s = 0.f;
#pragma unroll
        for (int j = 0; j < 32; j++) s += qp[j] * kp[j];
        sS[idx] = s * 0.17677669529663687f;
    }
    __syncthreads();

    // ---- softmax over k (NB*4*20 rows) ----
    if (tid < NB * 80) {
        float* row = sS + tid * 20;
        float m = row[0];
#pragma unroll
        for (int j = 1; j < 20; j++) m = fmaxf(m, row[j]);
        float s = 0.f;
#pragma unroll
        for (int j = 0; j < 20; j++) { float e2 = expf(row[j] - m); row[j] = e2; s += e2; }
        float inv = 1.f / s;
#pragma unroll
        for (int j = 0; j < 20; j++) row[j] *= inv;
    }
    __syncthreads();

    // ---- O = P @ V -> sA (overwrite Q, tf32) ----
    for (int i = tid; i < RROWS * 128; i += NT) {
        int r = i >> 7, d = i & 127;
        int node = r / 20, qi = r % 20, h = d >> 5;
        const float* pp = sS + ((node * 4 + h) * 20 + qi) * 20;
        const float* vp = sC + (node * 20) * LDA + d;
        float s = 0.f;
#pragma unroll
        for (int ki = 0; ki < 20; ki++) s += pp[ki] * vp[ki * LDA];
        sA[r * LDA + d] = to_tf32(s);
    }
    __syncthreads();

    // ---- X = O @ afc_w + afc_b + Z -> sB, then LN ----
    ACC_ZERO(acc);
    gemm128(acc, sA, afc_w, 128, 0, sW, tid);
    store_acc<0>(sB, acc, tid);
    __syncthreads();
    for (int i = tid; i < RROWS * 128; i += NT) {
        int r = i >> 7, d = i & 127;
        sB[r * LDA + d] = sB[r * LDA + d] + afc_b[d] + sZ[r * LDA + d];
    }
    __syncthreads();
    ln_rows60<1>(sB, aln_g, aln_b, scr, tid);

    // ---- FFN: 4 chunks of 128; X2 accumulated in registers ----
    float x2[2][4][4];
    ACC_ZERO(x2);
    for (int c = 0; c < 4; c++) {
        ACC_ZERO(acc);
        gemm128(acc, sB, f_w1, 512, c * 128, sW, tid);
        // epilogue: relu(+bias), tf32, -> sC
        {
            const int lane = tid & 31, w = tid >> 5;
            const int mg = w & 1, ng = w >> 1;
            const int qr = lane >> 2, qc = lane & 3;
#pragma unroll
            for (int mt = 0; mt < 2; mt++) {
                int r = (mg * 2 + mt) * 16 + qr;
#pragma unroll
                for (int nt = 0; nt < 4; nt++) {
                    int col = (ng * 4 + nt) * 8 + qc * 2;
                    float b0 = f_b1[c * 128 + col], b1 = f_b1[c * 128 + col + 1];
                    float v0 = fmaxf(acc[mt][nt][0] + b0, 0.f);
                    float v1 = fmaxf(acc[mt][nt][1] + b1, 0.f);
                    float v2 = fmaxf(acc[mt][nt][2] + b0, 0.f);
                    float v3 = fmaxf(acc[mt][nt][3] + b1, 0.f);
                    sC[r * LDA + col] = to_tf32(v0);
                    sC[r * LDA + col + 1] = to_tf32(v1);
                    sC[(r + 8) * LDA + col] = to_tf32(v2);
                    sC[(r + 8) * LDA + col + 1] = to_tf32(v3);
                }
            }
        }
        __syncthreads();
        gemm128(x2, sC, f_w2 + (size_t)c * 128 * 128, 128, 0, sW, tid);  // accumulate
    }
    // x2 + f_b2 + X -> sZ, then LN
    {
        const int lane = tid & 31, w = tid >> 5;
        const int mg = w & 1, ng = w >> 1;
        const int qr = lane >> 2, qc = lane & 3;
#pragma unroll
        for (int mt = 0; mt < 2; mt++) {
            int r = (mg * 2 + mt) * 16 + qr;
#pragma unroll
            for (int nt = 0; nt < 4; nt++) {
                int col = (ng * 4 + nt) * 8 + qc * 2;
                float b0 = f_b2[col], b1 = f_b2[col + 1];
                sZ[r * LDA + col] = x2[mt][nt][0] + b0 + sB[r * LDA + col];
                sZ[r * LDA + col + 1] = x2[mt][nt][1] + b1 + sB[r * LDA + col + 1];
                sZ[(r + 8) * LDA + col] = x2[mt][nt][2] + b0 + sB[(r + 8) * LDA + col];
                sZ[(r + 8) * LDA + col + 1] = x2[mt][nt][3] + b1 + sB[(r + 8) * LDA + col + 1];
            }
        }
    }
    __syncthreads();
    ln_rows60<0>(sZ, fln_g, fln_b, scr, tid);

    // ---- neighborhood mean -> scr ----
    for (int i = tid; i < NB * 128; i += NT) {
        int node = i >> 7, d = i & 127;
        float s = 0.f;
#pragma unroll
        for (int k = 0; k < 19; k++) s += sZ[(node * 20 + k) * LDA + d];
        scr[i] = s * (1.0f / 19.0f);
    }
    __syncthreads();

    // ---- fused @ f2n_w + gelu + residual -> sS ----
    for (int idx = tid; idx < NB * 128; idx += NT) {
        int node = idx >> 7, d = idx & 127;
        const float* selfr = sZ + (node * 20 + 19) * LDA;
        const float* neigh = scr + node * 128;
        float a = 0.f;
#pragma unroll 4
        for (int e = 0; e < 128; e++) a += selfr[e] * f2n_w[e * 128 + d];
#pragma unroll 4
        for (int e = 0; e < 128; e++) a += neigh[e] * f2n_w[(128 + e) * 128 + d];
        float y = gelu_exact(a + f2n_b[d]);
        if (node < nodes_here) y += nh[(size_t)(n0 + node) * 2560 + 19 * 128 + d];
        sS[node * 128 + d] = y;
    }
    __syncthreads();

    // ---- final LN per node, write out ----
    if (tid < NB) {
        float m = 0.f;
        for (int d = 0; d < 128; d++) m += sS[tid * 128 + d];
        m *= (1.0f / 128.0f);
        float v = 0.f;
        for (int d = 0; d < 128; d++) { float x = sS[tid * 128 + d] - m; v += x * x; }
        v *= (1.0f / 128.0f);
        scr[tid] = m;
        scr[NB + tid] = rsqrtf(v + 1e-5f);
    }
    __syncthreads();
    for (int idx = tid; idx < NB * 128; idx += NT) {
        int node = idx >> 7, d = idx & 127;
        if (node < nodes_here) {
            float y = (sS[node * 128 + d] - scr[node]) * scr[NB + node];
            out[(size_t)(n0 + node) * 128 + d] = y * oln_g[d] + oln_b[d];
        }
    }
}

extern "C" void kernel_launch(void* const* d_in, const int* in_sizes, int n_in,
                              void* d_out, int out_size) {
    (void)n_in; (void)out_size;
    const float* nh      = (const float*)d_in[0];
    const float* t       = (const float*)d_in[1];
    const float* t_now   = (const float*)d_in[2];
    const float* ef      = (const float*)d_in[3];
    const float* bfreq   = (const float*)d_in[4];
    const float* phase   = (const float*)d_in[5];
    const float* e_w     = (const float*)d_in[6];
    const float* e_b     = (const float*)d_in[7];
    const float* wq      = (const float*)d_in[8];
    const float* wk      = (const float*)d_in[9];
    const float* wv      = (const float*)d_in[10];
    const float* wq_src  = (const float*)d_in[11];
    const float* afc_w   = (const float*)d_in[12];
    const float* afc_b   = (const float*)d_in[13];
    const float* aln_g   = (const float*)d_in[14];
    const float* aln_b   = (const float*)d_in[15];
    const float* f_w1    = (const float*)d_in[16];
    const float* f_b1    = (const float*)d_in[17];
    const float* f_w2    = (const float*)d_in[18];
    const float* f_b2    = (const float*)d_in[19];
    const float* fln_g   = (const float*)d_in[20];
    const float* fln_b   = (const float*)d_in[21];
    const float* f2n_w   = (const float*)d_in[22];
    const float* f2n_b   = (const float*)d_in[23];
    const float* oln_g   = (const float*)d_in[24];
    const float* oln_b   = (const float*)d_in[25];
    float* out = (float*)d_out;

    const int N = in_sizes[0] / 2560;
    const int grid = (N + NB - 1) / NB;

    cudaFuncSetAttribute(tgat_kernel, cudaFuncAttributeMaxDynamicSharedMemorySize, SMEM_BYTES);
    tgat_kernel<<<grid, NT, SMEM_BYTES>>>(nh, t, t_now, ef, bfreq, phase, e_w, e_b,
                                          wq, wk, wv, wq_src, afc_w, afc_b, aln_g, aln_b,
                                          f_w1, f_b1, f_w2, f_b2, fln_g, fln_b,
                                          f2n_w, f2n_b, oln_g, oln_b, out, N);
}

// round 6
// speedup vs baseline: 2.8155x; 2.4835x over previous
#include <cuda_runtime.h>
#include <math.h>

#define LDA 132
#define LDW 136
#define NT 256
#define MAXROWS (20000*20)

__device__ float g_z[(size_t)MAXROWS*128];
__device__ float g_q[(size_t)MAXROWS*128];
__device__ float g_k[(size_t)MAXROWS*128];
__device__ float g_v[(size_t)MAXROWS*128];
__device__ float g_o[(size_t)MAXROWS*128];
__device__ float g_x[(size_t)MAXROWS*128];

__device__ __forceinline__ float gelu_exact(float x) {
    return 0.5f * x * (1.0f + erff(x * 0.7071067811865475f));
}
__device__ __forceinline__ float to_tf32(float x) {
    unsigned u;
    asm("cvt.rna.tf32.f32 %0, %1;" : "=r"(u) : "f"(x));
    return __uint_as_float(u);
}
__device__ __forceinline__ void mma_tf32(float d[4], const float a[4], const float b[2]) {
    asm volatile(
        "mma.sync.aligned.m16n8k8.row.col.f32.tf32.tf32.f32 "
        "{%0,%1,%2,%3}, {%4,%5,%6,%7}, {%8,%9}, {%0,%1,%2,%3};"
        : "+f"(d[0]), "+f"(d[1]), "+f"(d[2]), "+f"(d[3])
        : "r"(__float_as_uint(a[0])), "r"(__float_as_uint(a[1])),
          "r"(__float_as_uint(a[2])), "r"(__float_as_uint(a[3])),
          "r"(__float_as_uint(b[0])), "r"(__float_as_uint(b[1])));
}

#define ACC_ZERO(acc) do { _Pragma("unroll") for (int _m=0;_m<2;_m++) _Pragma("unroll") for (int _n=0;_n<4;_n++) { acc[_m][_n][0]=0.f;acc[_m][_n][1]=0.f;acc[_m][_n][2]=0.f;acc[_m][_n][3]=0.f; } } while(0)

// stage one 32-row k-chunk of W (128 cols from col0) into smem, tf32-rounded
__device__ __forceinline__ void stageW(float* dst, const float* __restrict__ W,
                                       int ldw, int krow0, int col0, int tid) {
#pragma unroll
    for (int j = 0; j < 4; j++) {
        int idx = tid + j * NT;
        int r = idx >> 5;
        int c4 = (idx & 31) << 2;
        float4 v = *(const float4*)(W + (size_t)(krow0 + r) * ldw + col0 + c4);
        float4 o;
        o.x = to_tf32(v.x); o.y = to_tf32(v.y); o.z = to_tf32(v.z); o.w = to_tf32(v.w);
        *(float4*)(dst + r * LDW + c4) = o;
    }
}

// stage 64 activation rows (128 cols, tf32) from global into sA[64][LDA]; rows >= rv zeroed
__device__ __forceinline__ void stageAct(float* sA, const float* __restrict__ g,
                                         long row0, int rv, int tid) {
#pragma unroll
    for (int j = 0; j < 8; j++) {
        int idx = tid + j * NT;
        int r = idx >> 5;
        int c4 = (idx & 31) << 2;
        float4 v = make_float4(0.f, 0.f, 0.f, 0.f);
        if (r < rv) v = *(const float4*)(g + (size_t)(row0 + r) * 128 + c4);
        float4 o;
        o.x = to_tf32(v.x); o.y = to_tf32(v.y); o.z = to_tf32(v.z); o.w = to_tf32(v.w);
        *(float4*)(sA + r * LDA + c4) = o;
    }
}

// acc[2][4][4] += sAct[64x128] @ W[128][128 cols from col0]; sWbuf double buffer 2x32xLDW
__device__ __forceinline__ void gemm128(float acc[2][4][4], const float* sAct,
                                        const float* __restrict__ Wg, int ldw, int col0,
                                        float* sWbuf, int tid) {
    const int lane = tid & 31, w = tid >> 5;
    const int mg = w & 1, ng = w >> 1;
    const int qr = lane >> 2, qc = lane & 3;
    stageW(sWbuf, Wg, ldw, 0, col0, tid);
    __syncthreads();
#pragma unroll
    for (int kc = 0; kc < 4; kc++) {
        const float* sw = sWbuf + (kc & 1) * (32 * LDW);
        if (kc < 3) stageW(sWbuf + ((kc + 1) & 1) * (32 * LDW), Wg, ldw, (kc + 1) * 32, col0, tid);
#pragma unroll
        for (int ks = 0; ks < 4; ks++) {
            const int k0 = kc * 32 + ks * 8;
            const int kl = ks * 8;
            float af[2][4];
#pragma unroll
            for (int mt = 0; mt < 2; mt++) {
                const float* ap = sAct + ((mg * 2 + mt) * 16 + qr) * LDA + k0 + qc;
                af[mt][0] = ap[0];
                af[mt][1] = ap[8 * LDA];
                af[mt][2] = ap[4];
                af[mt][3] = ap[8 * LDA + 4];
            }
#pragma unroll
            for (int nt = 0; nt < 4; nt++) {
                const float* bp = sw + (kl + qc) * LDW + (ng * 4 + nt) * 8 + qr;
                float bf[2];
                bf[0] = bp[0];
                bf[1] = bp[4 * LDW];
#pragma unroll
                for (int mt = 0; mt < 2; mt++) mma_tf32(acc[mt][nt], af[mt], bf);
            }
        }
        __syncthreads();
    }
}

// ------------------- kernel A: z -------------------
__global__ __launch_bounds__(NT, 2)
void k_z(const float* __restrict__ nh, const float* __restrict__ t,
         const float* __restrict__ t_now, const float* __restrict__ ef,
         const float* __restrict__ bfreq, const float* __restrict__ phase,
         const float* __restrict__ e_w, const float* __restrict__ e_b)
{
    extern __shared__ float sm[];
    float* sA = sm;
    float* sW = sm + 64 * LDA;
    const int tid = threadIdx.x;
    const long row0 = (long)blockIdx.x * 64;
    stageAct(sA, ef, row0, 64, tid);
    __syncthreads();
    float acc[2][4][4];
    ACC_ZERO(acc);
    gemm128(acc, sA, e_w, 128, 0, sW, tid);
    const float tn = t_now[0];
    const int lane = tid & 31, w = tid >> 5;
    const int mg = w & 1, ng = w >> 1;
    const int qr = lane >> 2, qc = lane & 3;
#pragma unroll
    for (int mt = 0; mt < 2; mt++) {
        long gr0 = row0 + (mg * 2 + mt) * 16 + qr;
        long gr1 = gr0 + 8;
        float tv0 = t[gr0], tv1 = t[gr1];
#pragma unroll
        for (int nt = 0; nt < 4; nt++) {
            int c = (ng * 4 + nt) * 8 + qc * 2;
#pragma unroll
            for (int p = 0; p < 2; p++) {
                int cc = c + p;
                float eb = e_b[cc], bf = bfreq[cc], ph = phase[cc];
                float v0 = gelu_exact(acc[mt][nt][p] + eb) + cosf((tn - tv0) * bf + ph)
                         + nh[(size_t)gr0 * 128 + cc];
                float v1 = gelu_exact(acc[mt][nt][2 + p] + eb) + cosf((tn - tv1) * bf + ph)
                         + nh[(size_t)gr1 * 128 + cc];
                g_z[(size_t)gr0 * 128 + cc] = to_tf32(v0);
                g_z[(size_t)gr1 * 128 + cc] = to_tf32(v1);
            }
        }
    }
}

// ------------------- kernel B: qkv -------------------
__device__ __forceinline__ void store_direct(float* __restrict__ g, long row0,
                                             float acc[2][4][4], int tid) {
    const int lane = tid & 31, w = tid >> 5;
    const int mg = w & 1, ng = w >> 1;
    const int qr = lane >> 2, qc = lane & 3;
#pragma unroll
    for (int mt = 0; mt < 2; mt++) {
        long r = row0 + (mg * 2 + mt) * 16 + qr;
#pragma unroll
        for (int nt = 0; nt < 4; nt++) {
            int c = (ng * 4 + nt) * 8 + qc * 2;
            float2 a0; a0.x = to_tf32(acc[mt][nt][0]); a0.y = to_tf32(acc[mt][nt][1]);
            float2 a1; a1.x = to_tf32(acc[mt][nt][2]); a1.y = to_tf32(acc[mt][nt][3]);
            *(float2*)(g + (size_t)r * 128 + c) = a0;
            *(float2*)(g + (size_t)(r + 8) * 128 + c) = a1;
        }
    }
}

__global__ __launch_bounds__(NT, 2)
void k_qkv(const float* __restrict__ wq, const float* __restrict__ wk,
           const float* __restrict__ wv)
{
    extern __shared__ float sm[];
    float* sA = sm;
    float* sW = sm + 64 * LDA;
    const int tid = threadIdx.x;
    const long row0 = (long)blockIdx.x * 64;
    stageAct(sA, g_z, row0, 64, tid);
    __syncthreads();
    float acc[2][4][4];
    ACC_ZERO(acc); gemm128(acc, sA, wq, 128, 0, sW, tid); store_direct(g_q, row0, acc, tid);
    ACC_ZERO(acc); gemm128(acc, sA, wk, 128, 0, sW, tid); store_direct(g_k, row0, acc, tid);
    ACC_ZERO(acc); gemm128(acc, sA, wv, 128, 0, sW, tid); store_direct(g_v, row0, acc, tid);
}

// ------------------- kernel C: self_q -------------------
__global__ __launch_bounds__(NT, 2)
void k_selfq(const float* __restrict__ wq_src, int Ntot)
{
    extern __shared__ float sm[];
    float* sA = sm;
    float* sW = sm + 64 * LDA;
    const int tid = threadIdx.x;
    const int n0 = blockIdx.x * 64;
    const int rv = min(64, Ntot - n0);
    // gather z rows (n*20+19)
#pragma unroll
    for (int j = 0; j < 8; j++) {
        int idx = tid + j * NT;
        int r = idx >> 5;
        int c4 = (idx & 31) << 2;
        float4 v = make_float4(0.f, 0.f, 0.f, 0.f);
        if (r < rv) v = *(const float4*)(g_z + ((size_t)(n0 + r) * 20 + 19) * 128 + c4);
        *(float4*)(sA + r * LDA + c4) = v;   // z already tf32
    }
    __syncthreads();
    float acc[2][4][4];
    ACC_ZERO(acc);
    gemm128(acc, sA, wq_src, 128, 0, sW, tid);
    const int lane = tid & 31, w = tid >> 5;
    const int mg = w & 1, ng = w >> 1;
    const int qr = lane >> 2, qc = lane & 3;
#pragma unroll
    for (int mt = 0; mt < 2; mt++) {
        int r = (mg * 2 + mt) * 16 + qr;
#pragma unroll
        for (int nt = 0; nt < 4; nt++) {
            int c = (ng * 4 + nt) * 8 + qc * 2;
#pragma unroll
            for (int hh = 0; hh < 2; hh++) {
                int rr = r + hh * 8;
                if (rr < rv) {
                    size_t go = ((size_t)(n0 + rr) * 20 + 19) * 128 + c;
                    float2 v;
                    v.x = to_tf32(acc[mt][nt][hh * 2]);
                    v.y = to_tf32(acc[mt][nt][hh * 2 + 1]);
                    *(float2*)(g_q + go) = v;
                    *(float2*)(g_k + go) = v;
                    *(float2*)(g_v + go) = v;
                }
            }
        }
    }
}

// ------------------- kernel D: attention -------------------
__global__ __launch_bounds__(NT, 2)
void k_attn()
{
    extern __shared__ float sm[];
    float* sq = sm;                 // 40 x LDA-ish (use 132 stride)
    float* sk = sm + 40 * 132;
    float* sv = sm + 80 * 132;
    float* ss = sm + 120 * 132;     // 3200 scores
    const int tid = threadIdx.x;
    const long n0 = (long)blockIdx.x * 2;
    const size_t gbase = (size_t)n0 * 20 * 128;
    for (int i = tid; i < 40 * 128; i += NT) {
        int r = i >> 7, d = i & 127;
        sq[r * 132 + d] = g_q[gbase + (size_t)r * 128 + d];
        sk[r * 132 + d] = g_k[gbase + (size_t)r * 128 + d];
        sv[r * 132 + d] = g_v[gbase + (size_t)r * 128 + d];
    }
    __syncthreads();
    for (int idx = tid; idx < 3200; idx += NT) {
        int node = idx / 1600, rem = idx % 1600;
        int h = rem / 400, qi = (rem / 20) % 20, ki = rem % 20;
        const float* qp = sq + (node * 20 + qi) * 132 + h * 32;
        const float* kp = sk + (node * 20 + ki) * 132 + h * 32;
        float s = 0.f;
#pragma unroll
        for (int j = 0; j < 32; j++) s += qp[j] * kp[j];
        ss[idx] = s * 0.17677669529663687f;
    }
    __syncthreads();
    if (tid < 160) {
        float* row = ss + tid * 20;
        float m = row[0];
#pragma unroll
        for (int j = 1; j < 20; j++) m = fmaxf(m, row[j]);
        float s = 0.f;
#pragma unroll
        for (int j = 0; j < 20; j++) { float e2 = expf(row[j] - m); row[j] = e2; s += e2; }
        float inv = 1.f / s;
#pragma unroll
        for (int j = 0; j < 20; j++) row[j] *= inv;
    }
    __syncthreads();
    for (int i = tid; i < 40 * 128; i += NT) {
        int r = i >> 7, d = i & 127;
        int node = r / 20, qi = r % 20, h = d >> 5;
        const float* pp = ss + ((node * 4 + h) * 20 + qi) * 20;
        const float* vp = sv + node * 20 * 132 + d;
        float s = 0.f;
#pragma unroll
        for (int ki = 0; ki < 20; ki++) s += pp[ki] * vp[ki * 132];
        g_o[gbase + (size_t)r * 128 + d] = s;
    }
}

// ------------------- kernel E: attn_fc + residual + LN -> x -------------------
__global__ __launch_bounds__(NT, 2)
void k_attnfc(const float* __restrict__ afc_w, const float* __restrict__ afc_b,
              const float* __restrict__ aln_g, const float* __restrict__ aln_b)
{
    extern __shared__ float sm[];
    float* sA = sm;
    float* sW = sm + 64 * LDA;
    float* scr = sW;   // reuse W buffer after gemm
    const int tid = threadIdx.x;
    const long row0 = (long)blockIdx.x * 64;
    stageAct(sA, g_o, row0, 64, tid);
    __syncthreads();
    float acc[2][4][4];
    ACC_ZERO(acc);
    gemm128(acc, sA, afc_w, 128, 0, sW, tid);
    // write acc back into sA
    {
        const int lane = tid & 31, w = tid >> 5;
        const int mg = w & 1, ng = w >> 1;
        const int qr = lane >> 2, qc = lane & 3;
#pragma unroll
        for (int mt = 0; mt < 2; mt++) {
            int r = (mg * 2 + mt) * 16 + qr;
#pragma unroll
            for (int nt = 0; nt < 4; nt++) {
                int c = (ng * 4 + nt) * 8 + qc * 2;
                sA[r * LDA + c] = acc[mt][nt][0];
                sA[r * LDA + c + 1] = acc[mt][nt][1];
                sA[(r + 8) * LDA + c] = acc[mt][nt][2];
                sA[(r + 8) * LDA + c + 1] = acc[mt][nt][3];
            }
        }
    }
    __syncthreads();
    for (int i = tid; i < 64 * 128; i += NT) {
        int r = i >> 7, d = i & 127;
        sA[r * LDA + d] += afc_b[d] + g_z[(size_t)(row0 + r) * 128 + d];
    }
    __syncthreads();
    if (tid < 64) {
        float m = 0.f;
#pragma unroll 8
        for (int dd = 0; dd < 128; dd++) m += sA[tid * LDA + ((dd + tid) & 127)];
        m *= (1.0f / 128.0f);
        float v = 0.f;
#pragma unroll 8
        for (int dd = 0; dd < 128; dd++) { float x = sA[tid * LDA + ((dd + tid) & 127)] - m; v += x * x; }
        v *= (1.0f / 128.0f);
        scr[tid] = m;
        scr[64 + tid] = rsqrtf(v + 1e-5f);
    }
    __syncthreads();
    for (int i = tid; i < 64 * 128; i += NT) {
        int r = i >> 7, d = i & 127;
        float y = (sA[r * LDA + d] - scr[r]) * scr[64 + r] * aln_g[d] + aln_b[d];
        g_x[(size_t)(row0 + r) * 128 + d] = to_tf32(y);
    }
}

// ------------------- kernel F: FFN + LN + fuse + out -------------------
__global__ __launch_bounds__(NT, 2)
void k_ffn(const float* __restrict__ f_w1, const float* __restrict__ f_b1,
           const float* __restrict__ f_w2, const float* __restrict__ f_b2,
           const float* __restrict__ fln_g, const float* __restrict__ fln_b,
           const float* __restrict__ f2n_w, const float* __restrict__ f2n_b,
           const float* __restrict__ oln_g, const float* __restrict__ oln_b,
           const float* __restrict__ nh, float* __restrict__ out, int Ntot)
{
    extern __shared__ float sm[];
    float* sX = sm;                       // 64*LDA
    float* sH = sX + 64 * LDA;            // 64*LDA
    float* sW = sH + 64 * LDA;            // 2*32*LDW
    float* scr = sW + 2 * 32 * LDW;       // 1024
    const int tid = threadIdx.x;
    const int nb0 = blockIdx.x * 3;
    const int nodes_here = min(3, Ntot - nb0);
    const int rows_here = nodes_here * 20;
    const long row0 = (long)nb0 * 20;

    stageAct(sX, g_x, row0, rows_here, tid);
    __syncthreads();

    float x2[2][4][4];
    ACC_ZERO(x2);
    const int lane = tid & 31, w = tid >> 5;
    const int mg = w & 1, ng = w >> 1;
    const int qr = lane >> 2, qc = lane & 3;

    for (int c = 0; c < 4; c++) {
        float acc[2][4][4];
        ACC_ZERO(acc);
        gemm128(acc, sX, f_w1, 512, c * 128, sW, tid);
#pragma unroll
        for (int mt = 0; mt < 2; mt++) {
            int r = (mg * 2 + mt) * 16 + qr;
#pragma unroll
            for (int nt = 0; nt < 4; nt++) {
                int col = (ng * 4 + nt) * 8 + qc * 2;
                float b0 = f_b1[c * 128 + col], b1 = f_b1[c * 128 + col + 1];
                sH[r * LDA + col]           = to_tf32(fmaxf(acc[mt][nt][0] + b0, 0.f));
                sH[r * LDA + col + 1]       = to_tf32(fmaxf(acc[mt][nt][1] + b1, 0.f));
                sH[(r + 8) * LDA + col]     = to_tf32(fmaxf(acc[mt][nt][2] + b0, 0.f));
                sH[(r + 8) * LDA + col + 1] = to_tf32(fmaxf(acc[mt][nt][3] + b1, 0.f));
            }
        }
        __syncthreads();
        gemm128(x2, sH, f_w2 + (size_t)c * 128 * 128, 128, 0, sW, tid);
    }

    // sH = x2 + b2 + x
#pragma unroll
    for (int mt = 0; mt < 2; mt++) {
        int r = (mg * 2 + mt) * 16 + qr;
#pragma unroll
        for (int nt = 0; nt < 4; nt++) {
            int col = (ng * 4 + nt) * 8 + qc * 2;
            float b0 = f_b2[col], b1 = f_b2[col + 1];
            sH[r * LDA + col]           = x2[mt][nt][0] + b0 + sX[r * LDA + col];
            sH[r * LDA + col + 1]       = x2[mt][nt][1] + b1 + sX[r * LDA + col + 1];
            sH[(r + 8) * LDA + col]     = x2[mt][nt][2] + b0 + sX[(r + 8) * LDA + col];
            sH[(r + 8) * LDA + col + 1] = x2[mt][nt][3] + b1 + sX[(r + 8) * LDA + col + 1];
        }
    }
    __syncthreads();

    // LN over rows_here rows
    if (tid < rows_here) {
        float m = 0.f;
#pragma unroll 8
        for (int dd = 0; dd < 128; dd++) m += sH[tid * LDA + ((dd + tid) & 127)];
        m *= (1.0f / 128.0f);
        float v = 0.f;
#pragma unroll 8
        for (int dd = 0; dd < 128; dd++) { float x = sH[tid * LDA + ((dd + tid) & 127)] - m; v += x * x; }
        v *= (1.0f / 128.0f);
        scr[tid] = m;
        scr[64 + tid] = rsqrtf(v + 1e-5f);
    }
    __syncthreads();
    for (int i = tid; i < rows_here * 128; i += NT) {
        int r = i >> 7, d = i & 127;
        sH[r * LDA + d] = (sH[r * LDA + d] - scr[r]) * scr[64 + r] * fln_g[d] + fln_b[d];
    }
    __syncthreads();

    float* sNe = scr + 128;   // 384
    float* sY  = scr + 512;   // 384
    for (int i = tid; i < nodes_here * 128; i += NT) {
        int node = i >> 7, d = i & 127;
        float s = 0.f;
#pragma unroll
        for (int k = 0; k < 19; k++) s += sH[(node * 20 + k) * LDA + d];
        sNe[i] = s * (1.0f / 19.0f);
    }
    __syncthreads();
    for (int idx = tid; idx < nodes_here * 128; idx += NT) {
        int node = idx >> 7, d = idx & 127;
        const float* selfr = sH + (node * 20 + 19) * LDA;
        const float* ne = sNe + node * 128;
        float a = 0.f;
#pragma unroll 4
        for (int e = 0; e < 128; e++) a += selfr[e] * f2n_w[e * 128 + d];
#pragma unroll 4
        for (int e = 0; e < 128; e++) a += ne[e] * f2n_w[(128 + e) * 128 + d];
        float y = gelu_exact(a + f2n_b[d])
                + nh[((size_t)(nb0 + node) * 20 + 19) * 128 + d];
        sY[idx] = y;
    }
    __syncthreads();
    if (tid < nodes_here) {
        float m = 0.f;
        for (int d = 0; d < 128; d++) m += sY[tid * 128 + d];
        m *= (1.0f / 128.0f);
        float v = 0.f;
        for (int d = 0; d < 128; d++) { float x = sY[tid * 128 + d] - m; v += x * x; }
        v *= (1.0f / 128.0f);
        scr[896 + tid] = m;
        scr[900 + tid] = rsqrtf(v + 1e-5f);
    }
    __syncthreads();
    for (int idx = tid; idx < nodes_here * 128; idx += NT) {
        int node = idx >> 7, d = idx & 127;
        float y = (sY[idx] - scr[896 + node]) * scr[900 + node];
        out[(size_t)(nb0 + node) * 128 + d] = y * oln_g[d] + oln_b[d];
    }
}

// ------------------- launch -------------------
#define SM_AB ((64 * LDA + 2 * 32 * LDW) * 4)
#define SM_D  ((120 * 132 + 3200) * 4)
#define SM_F  ((64 * LDA * 2 + 2 * 32 * LDW + 1024) * 4)

extern "C" void kernel_launch(void* const* d_in, const int* in_sizes, int n_in,
                              void* d_out, int out_size) {
    (void)n_in; (void)out_size;
    const float* nh      = (const float*)d_in[0];
    const float* t       = (const float*)d_in[1];
    const float* t_now   = (const float*)d_in[2];
    const float* ef      = (const float*)d_in[3];
    const float* bfreq   = (const float*)d_in[4];
    const float* phase   = (const float*)d_in[5];
    const float* e_w     = (const float*)d_in[6];
    const float* e_b     = (const float*)d_in[7];
    const float* wq      = (const float*)d_in[8];
    const float* wk      = (const float*)d_in[9];
    const float* wv      = (const float*)d_in[10];
    const float* wq_src  = (const float*)d_in[11];
    const float* afc_w   = (const float*)d_in[12];
    const float* afc_b   = (const float*)d_in[13];
    const float* aln_g   = (const float*)d_in[14];
    const float* aln_b   = (const float*)d_in[15];
    const float* f_w1    = (const float*)d_in[16];
    const float* f_b1    = (const float*)d_in[17];
    const float* f_w2    = (const float*)d_in[18];
    const float* f_b2    = (const float*)d_in[19];
    const float* fln_g   = (const float*)d_in[20];
    const float* fln_b   = (const float*)d_in[21];
    const float* f2n_w   = (const float*)d_in[22];
    const float* f2n_b   = (const float*)d_in[23];
    const float* oln_g   = (const float*)d_in[24];
    const float* oln_b   = (const float*)d_in[25];
    float* out = (float*)d_out;

    const int N = in_sizes[0] / 2560;
    const int totrows = N * 20;
    const int gM = totrows / 64;            // exact for N=20000

    cudaFuncSetAttribute(k_z,      cudaFuncAttributeMaxDynamicSharedMemorySize, SM_AB);
    cudaFuncSetAttribute(k_qkv,    cudaFuncAttributeMaxDynamicSharedMemorySize, SM_AB);
    cudaFuncSetAttribute(k_selfq,  cudaFuncAttributeMaxDynamicSharedMemorySize, SM_AB);
    cudaFuncSetAttribute(k_attn,   cudaFuncAttributeMaxDynamicSharedMemorySize, SM_D);
    cudaFuncSetAttribute(k_attnfc, cudaFuncAttributeMaxDynamicSharedMemorySize, SM_AB);
    cudaFuncSetAttribute(k_ffn,    cudaFuncAttributeMaxDynamicSharedMemorySize, SM_F);

    k_z<<<gM, NT, SM_AB>>>(nh, t, t_now, ef, bfreq, phase, e_w, e_b);
    k_qkv<<<gM, NT, SM_AB>>>(wq, wk, wv);
    k_selfq<<<(N + 63) / 64, NT, SM_AB>>>(wq_src, N);
    k_attn<<<N / 2, NT, SM_D>>>();
    k_attnfc<<<gM, NT, SM_AB>>>(afc_w, afc_b, aln_g, aln_b);
    k_ffn<<<(N + 2) / 3, NT, SM_F>>>(f_w1, f_b1, f_w2, f_b2, fln_g, fln_b,
                                     f2n_w, f2n_b, oln_g, oln_b, nh, out, N);
}

// round 8
// speedup vs baseline: 3.1924x; 1.1339x over previous
#include <cuda_runtime.h>
#include <math.h>

#define LDA 132
#define LDW 136
#define NT 256
#define MAXROWS (20000*20)

__device__ float g_z[(size_t)MAXROWS*128];
__device__ float g_q[(size_t)MAXROWS*128];
__device__ float g_k[(size_t)MAXROWS*128];
__device__ float g_v[(size_t)MAXROWS*128];
__device__ float g_o[(size_t)MAXROWS*128];
__device__ float g_x[(size_t)MAXROWS*128];

// preconverted tf32 weights
#define W_EW  0
#define W_Q   16384
#define W_K   32768
#define W_V   49152
#define W_QS  65536
#define W_AFC 81920
#define W_F1  98304
#define W_F2  163840
#define W_TOT 229376
__device__ float g_wbuf[W_TOT];

__device__ __forceinline__ float gelu_exact(float x) {
    return 0.5f * x * (1.0f + erff(x * 0.7071067811865475f));
}
__device__ __forceinline__ float to_tf32(float x) {
    unsigned u;
    asm("cvt.rna.tf32.f32 %0, %1;" : "=r"(u) : "f"(x));
    return __uint_as_float(u);
}
__device__ __forceinline__ void mma_tf32(float d[4], const float a[4], const float b[2]) {
    asm volatile(
        "mma.sync.aligned.m16n8k8.row.col.f32.tf32.tf32.f32 "
        "{%0,%1,%2,%3}, {%4,%5,%6,%7}, {%8,%9}, {%0,%1,%2,%3};"
        : "+f"(d[0]), "+f"(d[1]), "+f"(d[2]), "+f"(d[3])
        : "r"(__float_as_uint(a[0])), "r"(__float_as_uint(a[1])),
          "r"(__float_as_uint(a[2])), "r"(__float_as_uint(a[3])),
          "r"(__float_as_uint(b[0])), "r"(__float_as_uint(b[1])));
}

#define ACC_ZERO(acc) do { _Pragma("unroll") for (int _m=0;_m<2;_m++) _Pragma("unroll") for (int _n=0;_n<4;_n++) { acc[_m][_n][0]=0.f;acc[_m][_n][1]=0.f;acc[_m][_n][2]=0.f;acc[_m][_n][3]=0.f; } } while(0)

__device__ __forceinline__ void cpa16(float* dst, const float* src) {
    unsigned u = (unsigned)__cvta_generic_to_shared(dst);
    asm volatile("cp.async.cg.shared.global [%0], [%1], 16;\n" :: "r"(u), "l"(src));
}
#define CP_COMMIT() asm volatile("cp.async.commit_group;\n")
#define CP_WAIT(n)  asm volatile("cp.async.wait_group %0;\n" :: "n"(n))

// stage one 32-row k-chunk of preconverted tf32 W via cp.async
__device__ __forceinline__ void stageWa(float* dst, const float* __restrict__ W,
                                        int ldw, int krow0, int col0, int tid) {
#pragma unroll
    for (int j = 0; j < 4; j++) {
        int idx = tid + j * NT;
        int r = idx >> 5;
        int c4 = (idx & 31) << 2;
        cpa16(dst + r * LDW + c4, W + (size_t)(krow0 + r) * ldw + col0 + c4);
    }
}

// stage 64 rows of tf32-valued activations via cp.async; rows >= rv zero-filled
__device__ __forceinline__ void stageActa(float* sA, const float* __restrict__ g,
                                          long row0, int rv, int tid) {
#pragma unroll
    for (int j = 0; j < 8; j++) {
        int idx = tid + j * NT;
        int r = idx >> 5;
        int c4 = (idx & 31) << 2;
        if (r < rv) cpa16(sA + r * LDA + c4, g + (size_t)(row0 + r) * 128 + c4);
        else *(float4*)(sA + r * LDA + c4) = make_float4(0.f, 0.f, 0.f, 0.f);
    }
    CP_COMMIT();
}

// acc += sAct[64x128] @ W(tf32, global)[128][128 cols from col0]; cp.async double buffer
__device__ __forceinline__ void gemm128a(float acc[2][4][4], const float* sAct,
                                         const float* __restrict__ Wg, int ldw, int col0,
                                         float* sWbuf, int tid) {
    const int lane = tid & 31, w = tid >> 5;
    const int mg = w & 1, ng = w >> 1;
    const int qr = lane >> 2, qc = lane & 3;
    stageWa(sWbuf, Wg, ldw, 0, col0, tid);
    CP_COMMIT();
#pragma unroll
    for (int kc = 0; kc < 4; kc++) {
        const float* sw = sWbuf + (kc & 1) * (32 * LDW);
        if (kc < 3) {
            stageWa(sWbuf + ((kc + 1) & 1) * (32 * LDW), Wg, ldw, (kc + 1) * 32, col0, tid);
            CP_COMMIT();
            CP_WAIT(1);
        } else {
            CP_WAIT(0);
        }
        __syncthreads();
#pragma unroll
        for (int ks = 0; ks < 4; ks++) {
            const int k0 = kc * 32 + ks * 8;
            const int kl = ks * 8;
            float af[2][4];
#pragma unroll
            for (int mt = 0; mt < 2; mt++) {
                const float* ap = sAct + ((mg * 2 + mt) * 16 + qr) * LDA + k0 + qc;
                af[mt][0] = ap[0];
                af[mt][1] = ap[8 * LDA];
                af[mt][2] = ap[4];
                af[mt][3] = ap[8 * LDA + 4];
            }
#pragma unroll
            for (int nt = 0; nt < 4; nt++) {
                const float* bp = sw + (kl + qc) * LDW + (ng * 4 + nt) * 8 + qr;
                float bf[2];
                bf[0] = bp[0];
                bf[1] = bp[4 * LDW];
#pragma unroll
                for (int mt = 0; mt < 2; mt++) mma_tf32(acc[mt][nt], af[mt], bf);
            }
        }
        __syncthreads();
    }
}

__device__ __forceinline__ void store_direct(float* __restrict__ g, long row0,
                                             float acc[2][4][4], int tid) {
    const int lane = tid & 31, w = tid >> 5;
    const int mg = w & 1, ng = w >> 1;
    const int qr = lane >> 2, qc = lane & 3;
#pragma unroll
    for (int mt = 0; mt < 2; mt++) {
        long r = row0 + (mg * 2 + mt) * 16 + qr;
#pragma unroll
        for (int nt = 0; nt < 4; nt++) {
            int c = (ng * 4 + nt) * 8 + qc * 2;
            float2 a0; a0.x = to_tf32(acc[mt][nt][0]); a0.y = to_tf32(acc[mt][nt][1]);
            float2 a1; a1.x = to_tf32(acc[mt][nt][2]); a1.y = to_tf32(acc[mt][nt][3]);
            *(float2*)(g + (size_t)r * 128 + c) = a0;
            *(float2*)(g + (size_t)(r + 8) * 128 + c) = a1;
        }
    }
}

// ------------------- kernel 0: preconvert weights to tf32 -------------------
__global__ void k_prep(const float* __restrict__ e_w, const float* __restrict__ wq,
                       const float* __restrict__ wk, const float* __restrict__ wv,
                       const float* __restrict__ wq_src, const float* __restrict__ afc_w,
                       const float* __restrict__ f_w1, const float* __restrict__ f_w2)
{
    int i = blockIdx.x * 256 + threadIdx.x;
    if (i >= W_TOT) return;
    const float* src; int off;
    if      (i < W_Q)   { src = e_w;    off = W_EW; }
    else if (i < W_K)   { src = wq;     off = W_Q; }
    else if (i < W_V)   { src = wk;     off = W_K; }
    else if (i < W_QS)  { src = wv;     off = W_V; }
    else if (i < W_AFC) { src = wq_src; off = W_QS; }
    else if (i < W_F1)  { src = afc_w;  off = W_AFC; }
    else if (i < W_F2)  { src = f_w1;   off = W_F1; }
    else                { src = f_w2;   off = W_F2; }
    g_wbuf[i] = to_tf32(src[i - off]);
}

// ------------------- kernel 1: z + qkv fused -------------------
__global__ __launch_bounds__(NT, 2)
void k_zqkv(const float* __restrict__ nh, const float* __restrict__ t,
            const float* __restrict__ t_now, const float* __restrict__ ef,
            const float* __restrict__ bfreq, const float* __restrict__ phase,
            const float* __restrict__ e_b, long totrows)
{
    extern __shared__ float sm[];
    float* sA = sm;                   // ef, then reused only by gemm reads
    float* sZ = sm + 64 * LDA;
    float* sW = sZ + 64 * LDA;
    const int tid = threadIdx.x;
    const long row0 = (long)blockIdx.x * 64;
    const int rv = (int)min((long)64, totrows - row0);

    // stage ef (raw fp32 -> tf32, synchronous path)
#pragma unroll
    for (int j = 0; j < 8; j++) {
        int idx = tid + j * NT;
        int r = idx >> 5;
        int c4 = (idx & 31) << 2;
        float4 v = make_float4(0.f, 0.f, 0.f, 0.f);
        if (r < rv) v = *(const float4*)(ef + (size_t)(row0 + r) * 128 + c4);
        float4 o;
        o.x = to_tf32(v.x); o.y = to_tf32(v.y); o.z = to_tf32(v.z); o.w = to_tf32(v.w);
        *(float4*)(sA + r * LDA + c4) = o;
    }
    __syncthreads();

    float acc[2][4][4];
    ACC_ZERO(acc);
    gemm128a(acc, sA, g_wbuf + W_EW, 128, 0, sW, tid);

    // epilogue: z = nh + gelu(E+e_b) + cos((tn-t)f+ph) -> sZ (tf32) + g_z
    const float tn = t_now[0];
    const int lane = tid & 31, w = tid >> 5;
    const int mg = w & 1, ng = w >> 1;
    const int qr = lane >> 2, qc = lane & 3;
#pragma unroll
    for (int mt = 0; mt < 2; mt++) {
        int lr0 = (mg * 2 + mt) * 16 + qr;
#pragma unroll
        for (int hh = 0; hh < 2; hh++) {
            int lr = lr0 + hh * 8;
            long gr = row0 + lr;
            bool ok = (lr < rv);
            float tv = ok ? t[gr] : 0.f;
#pragma unroll
            for (int nt = 0; nt < 4; nt++) {
                int c = (ng * 4 + nt) * 8 + qc * 2;
#pragma unroll
                for (int p = 0; p < 2; p++) {
                    int cc = c + p;
                    float zv = 0.f;
                    if (ok) {
                        float g = gelu_exact(acc[mt][nt][hh * 2 + p] + e_b[cc]);
                        float te = cosf((tn - tv) * bfreq[cc] + phase[cc]);
                        zv = to_tf32(nh[(size_t)gr * 128 + cc] + g + te);
                        g_z[(size_t)gr * 128 + cc] = zv;
                    }
                    sZ[lr * LDA + cc] = zv;
                }
            }
        }
    }
    __syncthreads();

    ACC_ZERO(acc); gemm128a(acc, sZ, g_wbuf + W_Q, 128, 0, sW, tid);
    if (rv == 64) store_direct(g_q, row0, acc, tid);
    else { const int rvv = rv;
#pragma unroll
        for (int mt = 0; mt < 2; mt++) {
            int lr0 = (mg * 2 + mt) * 16 + qr;
#pragma unroll
            for (int hh = 0; hh < 2; hh++) {
                int lr = lr0 + hh * 8;
                if (lr < rvv)
#pragma unroll
                    for (int nt = 0; nt < 4; nt++) {
                        int c = (ng * 4 + nt) * 8 + qc * 2;
                        float2 a; a.x = to_tf32(acc[mt][nt][hh*2]); a.y = to_tf32(acc[mt][nt][hh*2+1]);
                        *(float2*)(g_q + (size_t)(row0 + lr) * 128 + c) = a;
                    }
            }
        }
    }
    ACC_ZERO(acc); gemm128a(acc, sZ, g_wbuf + W_K, 128, 0, sW, tid);
    if (rv == 64) store_direct(g_k, row0, acc, tid);
    ACC_ZERO(acc); gemm128a(acc, sZ, g_wbuf + W_V, 128, 0, sW, tid);
    if (rv == 64) store_direct(g_v, row0, acc, tid);
}

// ------------------- kernel 2: self_q -------------------
__global__ __launch_bounds__(NT, 2)
void k_selfq(int Ntot)
{
    extern __shared__ float sm[];
    float* sA = sm;
    float* sW = sm + 64 * LDA;
    const int tid = threadIdx.x;
    const int n0 = blockIdx.x * 64;
    const int rv = min(64, Ntot - n0);
#pragma unroll
    for (int j = 0; j < 8; j++) {
        int idx = tid + j * NT;
        int r = idx >> 5;
        int c4 = (idx & 31) << 2;
        if (r < rv) cpa16(sA + r * LDA + c4, g_z + ((size_t)(n0 + r) * 20 + 19) * 128 + c4);
        else *(float4*)(sA + r * LDA + c4) = make_float4(0.f, 0.f, 0.f, 0.f);
    }
    CP_COMMIT();
    float acc[2][4][4];
    ACC_ZERO(acc);
    gemm128a(acc, sA, g_wbuf + W_QS, 128, 0, sW, tid);
    const int lane = tid & 31, w = tid >> 5;
    const int mg = w & 1, ng = w >> 1;
    const int qr = lane >> 2, qc = lane & 3;
#pragma unroll
    for (int mt = 0; mt < 2; mt++) {
        int r = (mg * 2 + mt) * 16 + qr;
#pragma unroll
        for (int nt = 0; nt < 4; nt++) {
            int c = (ng * 4 + nt) * 8 + qc * 2;
#pragma unroll
            for (int hh = 0; hh < 2; hh++) {
                int rr = r + hh * 8;
                if (rr < rv) {
                    size_t go = ((size_t)(n0 + rr) * 20 + 19) * 128 + c;
                    float2 v;
                    v.x = to_tf32(acc[mt][nt][hh * 2]);
                    v.y = to_tf32(acc[mt][nt][hh * 2 + 1]);
                    *(float2*)(g_q + go) = v;
                    *(float2*)(g_k + go) = v;
                    *(float2*)(g_v + go) = v;
                }
            }
        }
    }
}

// ------------------- kernel 3: attention (register-resident, 3 nodes/CTA) ----
__global__ __launch_bounds__(NT, 2)
void k_attn(int Ntot)
{
    extern __shared__ float sm[];
    float* sq = sm;                  // [60][132]
    float* sk = sm + 60 * 132;
    float* sv = sm + 120 * 132;
    const int tid = threadIdx.x;
    const int nb0 = blockIdx.x * 3;
    const int nodes_here = min(3, Ntot - nb0);
    const int rows = nodes_here * 20;
    const size_t gbase = (size_t)nb0 * 20 * 128;

    for (int i = tid; i < rows * 32; i += NT) {
        int r = i >> 5, c4 = (i & 31) << 2;
        *(float4*)(sq + r * 132 + c4) = *(const float4*)(g_q + gbase + (size_t)r * 128 + c4);
        *(float4*)(sk + r * 132 + c4) = *(const float4*)(g_k + gbase + (size_t)r * 128 + c4);
        *(float4*)(sv + r * 132 + c4) = *(const float4*)(g_v + gbase + (size_t)r * 128 + c4);
    }
    __syncthreads();

    const int node = tid / 80, h = (tid / 20) % 4, qi = tid % 20;
    const bool active = tid < nodes_here * 80;
    float oacc[32];
    if (active) {
        float qreg[32];
        const float* qp = sq + (node * 20 + qi) * 132 + h * 32;
#pragma unroll
        for (int j = 0; j < 8; j++) {
            float4 v = *(const float4*)(qp + j * 4);
            qreg[4*j] = v.x; qreg[4*j+1] = v.y; qreg[4*j+2] = v.z; qreg[4*j+3] = v.w;
        }
        float p[20];
#pragma unroll
        for (int ki = 0; ki < 20; ki++) {
            const float* kp = sk + (node * 20 + ki) * 132 + h * 32;
            float s = 0.f;
#pragma unroll
            for (int j = 0; j < 8; j++) {
                float4 kv = *(const float4*)(kp + j * 4);
                s += qreg[4*j] * kv.x + qreg[4*j+1] * kv.y + qreg[4*j+2] * kv.z + qreg[4*j+3] * kv.w;
            }
            p[ki] = s * 0.17677669529663687f;
        }
        float m = p[0];
#pragma unroll
        for (int ki = 1; ki < 20; ki++) m = fmaxf(m, p[ki]);
        float ssum = 0.f;
#pragma unroll
        for (int ki = 0; ki < 20; ki++) { p[ki] = expf(p[ki] - m); ssum += p[ki]; }
        float inv = 1.f / ssum;
#pragma unroll
        for (int j = 0; j < 32; j++) oacc[j] = 0.f;
#pragma unroll
        for (int ki = 0; ki < 20; ki++) {
            float pw = p[ki] * inv;
            const float* vp = sv + (node * 20 + ki) * 132 + h * 32;
#pragma unroll
            for (int j = 0; j < 8; j++) {
                float4 vv = *(const float4*)(vp + j * 4);
                oacc[4*j]   += pw * vv.x; oacc[4*j+1] += pw * vv.y;
                oacc[4*j+2] += pw * vv.z; oacc[4*j+3] += pw * vv.w;
            }
        }
    }
    __syncthreads();
    if (active) {
        float* op = sq + (node * 20 + qi) * 132 + h * 32;
#pragma unroll
        for (int j = 0; j < 8; j++) {
            float4 v;
            v.x = to_tf32(oacc[4*j]);   v.y = to_tf32(oacc[4*j+1]);
            v.z = to_tf32(oacc[4*j+2]); v.w = to_tf32(oacc[4*j+3]);
            *(float4*)(op + j * 4) = v;
        }
    }
    __syncthreads();
    for (int i = tid; i < rows * 32; i += NT) {
        int r = i >> 5, c4 = (i & 31) << 2;
        *(float4*)(g_o + gbase + (size_t)r * 128 + c4) = *(const float4*)(sq + r * 132 + c4);
    }
}

// ------------------- kernel 4: attn_fc + residual + LN -> x -------------------
__global__ __launch_bounds__(NT, 2)
void k_attnfc(const float* __restrict__ afc_b, const float* __restrict__ aln_g,
              const float* __restrict__ aln_b, long totrows)
{
    extern __shared__ float sm[];
    float* sA = sm;
    float* sW = sm + 64 * LDA;
    float* scr = sW;
    const int tid = threadIdx.x;
    const long row0 = (long)blockIdx.x * 64;
    const int rv = (int)min((long)64, totrows - row0);
    stageActa(sA, g_o, row0, rv, tid);
    float acc[2][4][4];
    ACC_ZERO(acc);
    gemm128a(acc, sA, g_wbuf + W_AFC, 128, 0, sW, tid);
    {
        const int lane = tid & 31, w = tid >> 5;
        const int mg = w & 1, ng = w >> 1;
        const int qr = lane >> 2, qc = lane & 3;
#pragma unroll
        for (int mt = 0; mt < 2; mt++) {
            int r = (mg * 2 + mt) * 16 + qr;
#pragma unroll
            for (int nt = 0; nt < 4; nt++) {
                int c = (ng * 4 + nt) * 8 + qc * 2;
                sA[r * LDA + c] = acc[mt][nt][0];
                sA[r * LDA + c + 1] = acc[mt][nt][1];
                sA[(r + 8) * LDA + c] = acc[mt][nt][2];
                sA[(r + 8) * LDA + c + 1] = acc[mt][nt][3];
            }
        }
    }
    __syncthreads();
    for (int i = tid; i < 64 * 128; i += NT) {
        int r = i >> 7, d = i & 127;
        if (r < rv) sA[r * LDA + d] += afc_b[d] + g_z[(size_t)(row0 + r) * 128 + d];
    }
    __syncthreads();
    if (tid < 64) {
        float m = 0.f;
#pragma unroll 8
        for (int dd = 0; dd < 128; dd++) m += sA[tid * LDA + ((dd + tid) & 127)];
        m *= (1.0f / 128.0f);
        float v = 0.f;
#pragma unroll 8
        for (int dd = 0; dd < 128; dd++) { float x = sA[tid * LDA + ((dd + tid) & 127)] - m; v += x * x; }
        v *= (1.0f / 128.0f);
        scr[tid] = m;
        scr[64 + tid] = rsqrtf(v + 1e-5f);
    }
    __syncthreads();
    for (int i = tid; i < 64 * 128; i += NT) {
        int r = i >> 7, d = i & 127;
        if (r < rv) {
            float y = (sA[r * LDA + d] - scr[r]) * scr[64 + r] * aln_g[d] + aln_b[d];
            g_x[(size_t)(row0 + r) * 128 + d] = to_tf32(y);
        }
    }
}

// ------------------- kernel 5: FFN + LN + fuse + out -------------------
__global__ __launch_bounds__(NT, 2)
void k_ffn(const float* __restrict__ f_b1, const float* __restrict__ f_b2,
           const float* __restrict__ fln_g, const float* __restrict__ fln_b,
           const float* __restrict__ f2n_w, const float* __restrict__ f2n_b,
           const float* __restrict__ oln_g, const float* __restrict__ oln_b,
           const float* __restrict__ nh, float* __restrict__ out, int Ntot)
{
    extern __shared__ float sm[];
    float* sX = sm;
    float* sH = sX + 64 * LDA;
    float* sW = sH + 64 * LDA;
    float* scr = sW + 2 * 32 * LDW;
    const int tid = threadIdx.x;
    const int nb0 = blockIdx.x * 3;
    const int nodes_here = min(3, Ntot - nb0);
    const int rows_here = nodes_here * 20;
    const long row0 = (long)nb0 * 20;

    stageActa(sX, g_x, row0, rows_here, tid);

    float x2[2][4][4];
    ACC_ZERO(x2);
    const int lane = tid & 31, w = tid >> 5;
    const int mg = w & 1, ng = w >> 1;
    const int qr = lane >> 2, qc = lane & 3;

    for (int c = 0; c < 4; c++) {
        float acc[2][4][4];
        ACC_ZERO(acc);
        gemm128a(acc, sX, g_wbuf + W_F1, 512, c * 128, sW, tid);
#pragma unroll
        for (int mt = 0; mt < 2; mt++) {
            int r = (mg * 2 + mt) * 16 + qr;
#pragma unroll
            for (int nt = 0; nt < 4; nt++) {
                int col = (ng * 4 + nt) * 8 + qc * 2;
                float b0 = f_b1[c * 128 + col], b1 = f_b1[c * 128 + col + 1];
                sH[r * LDA + col]           = to_tf32(fmaxf(acc[mt][nt][0] + b0, 0.f));
                sH[r * LDA + col + 1]       = to_tf32(fmaxf(acc[mt][nt][1] + b1, 0.f));
                sH[(r + 8) * LDA + col]     = to_tf32(fmaxf(acc[mt][nt][2] + b0, 0.f));
                sH[(r + 8) * LDA + col + 1] = to_tf32(fmaxf(acc[mt][nt][3] + b1, 0.f));
            }
        }
        __syncthreads();
        gemm128a(x2, sH, g_wbuf + W_F2 + (size_t)c * 128 * 128, 128, 0, sW, tid);
    }

#pragma unroll
    for (int mt = 0; mt < 2; mt++) {
        int r = (mg * 2 + mt) * 16 + qr;
#pragma unroll
        for (int nt = 0; nt < 4; nt++) {
            int col = (ng * 4 + nt) * 8 + qc * 2;
            float b0 = f_b2[col], b1 = f_b2[col + 1];
            sH[r * LDA + col]           = x2[mt][nt][0] + b0 + sX[r * LDA + col];
            sH[r * LDA + col + 1]       = x2[mt][nt][1] + b1 + sX[r * LDA + col + 1];
            sH[(r + 8) * LDA + col]     = x2[mt][nt][2] + b0 + sX[(r + 8) * LDA + col];
            sH[(r + 8) * LDA + col + 1] = x2[mt][nt][3] + b1 + sX[(r + 8) * LDA + col + 1];
        }
    }
    __syncthreads();

    if (tid < rows_here) {
        float m = 0.f;
#pragma unroll 8
        for (int dd = 0; dd < 128; dd++) m += sH[tid * LDA + ((dd + tid) & 127)];
        m *= (1.0f / 128.0f);
        float v = 0.f;
#pragma unroll 8
        for (int dd = 0; dd < 128; dd++) { float x = sH[tid * LDA + ((dd + tid) & 127)] - m; v += x * x; }
        v *= (1.0f / 128.0f);
        scr[tid] = m;
        scr[64 + tid] = rsqrtf(v + 1e-5f);
    }
    __syncthreads();
    for (int i = tid; i < rows_here * 128; i += NT) {
        int r = i >> 7, d = i & 127;
        sH[r * LDA + d] = (sH[r * LDA + d] - scr[r]) * scr[64 + r] * fln_g[d] + fln_b[d];
    }
    __syncthreads();

    float* sNe = scr + 128;
    float* sY  = scr + 512;
    for (int i = tid; i < nodes_here * 128; i += NT) {
        int node = i >> 7, d = i & 127;
        float s = 0.f;
#pragma unroll
        for (int k = 0; k < 19; k++) s += sH[(node * 20 + k) * LDA + d];
        sNe[i] = s * (1.0f / 19.0f);
    }
    __syncthreads();
    for (int idx = tid; idx < nodes_here * 128; idx += NT) {
        int node = idx >> 7, d = idx & 127;
        const float* selfr = sH + (node * 20 + 19) * LDA;
        const float* ne = sNe + node * 128;
        float a = 0.f;
#pragma unroll 4
        for (int e = 0; e < 128; e++) a += selfr[e] * f2n_w[e * 128 + d];
#pragma unroll 4
        for (int e = 0; e < 128; e++) a += ne[e] * f2n_w[(128 + e) * 128 + d];
        float y = gelu_exact(a + f2n_b[d])
                + nh[((size_t)(nb0 + node) * 20 + 19) * 128 + d];
        sY[idx] = y;
    }
    __syncthreads();
    if (tid < nodes_here) {
        float m = 0.f;
        for (int d = 0; d < 128; d++) m += sY[tid * 128 + d];
        m *= (1.0f / 128.0f);
        float v = 0.f;
        for (int d = 0; d < 128; d++) { float x = sY[tid * 128 + d] - m; v += x * x; }
        v *= (1.0f / 128.0f);
        scr[896 + tid] = m;
        scr[900 + tid] = rsqrtf(v + 1e-5f);
    }
    __syncthreads();
    for (int idx = tid; idx < nodes_here * 128; idx += NT) {
        int node = idx >> 7, d = idx & 127;
        float y = (sY[idx] - scr[896 + node]) * scr[900 + node];
        out[(size_t)(nb0 + node) * 128 + d] = y * oln_g[d] + oln_b[d];
    }
}

// ------------------- launch -------------------
#define SM_ZQKV ((2 * 64 * LDA + 2 * 32 * LDW) * 4)
#define SM_AB   ((64 * LDA + 2 * 32 * LDW) * 4)
#define SM_ATT  (180 * 132 * 4)
#define SM_F    ((64 * LDA * 2 + 2 * 32 * LDW + 1024) * 4)

extern "C" void kernel_launch(void* const* d_in, const int* in_sizes, int n_in,
                              void* d_out, int out_size) {
    (void)n_in; (void)out_size;
    const float* nh      = (const float*)d_in[0];
    const float* t       = (const float*)d_in[1];
    const float* t_now   = (const float*)d_in[2];
    const float* ef      = (const float*)d_in[3];
    const float* bfreq   = (const float*)d_in[4];
    const float* phase   = (const float*)d_in[5];
    const float* e_w     = (const float*)d_in[6];
    const float* e_b     = (const float*)d_in[7];
    const float* wq      = (const float*)d_in[8];
    const float* wk      = (const float*)d_in[9];
    const float* wv      = (const float*)d_in[10];
    const float* wq_src  = (const float*)d_in[11];
    const float* afc_w   = (const float*)d_in[12];
    const float* afc_b   = (const float*)d_in[13];
    const float* aln_g   = (const float*)d_in[14];
    const float* aln_b   = (const float*)d_in[15];
    const float* f_w1    = (const float*)d_in[16];
    const float* f_b1    = (const float*)d_in[17];
    const float* f_w2    = (const float*)d_in[18];
    const float* f_b2    = (const float*)d_in[19];
    const float* fln_g   = (const float*)d_in[20];
    const float* fln_b   = (const float*)d_in[21];
    const float* f2n_w   = (const float*)d_in[22];
    const float* f2n_b   = (const float*)d_in[23];
    const float* oln_g   = (const float*)d_in[24];
    const float* oln_b   = (const float*)d_in[25];
    float* out = (float*)d_out;

    const int N = in_sizes[0] / 2560;
    const long totrows = (long)N * 20;
    const int gM = (int)((totrows + 63) / 64);

    cudaFuncSetAttribute(k_zqkv,   cudaFuncAttributeMaxDynamicSharedMemorySize, SM_ZQKV);
    cudaFuncSetAttribute(k_selfq,  cudaFuncAttributeMaxDynamicSharedMemorySize, SM_AB);
    cudaFuncSetAttribute(k_attn,   cudaFuncAttributeMaxDynamicSharedMemorySize, SM_ATT);
    cudaFuncSetAttribute(k_attnfc, cudaFuncAttributeMaxDynamicSharedMemorySize, SM_AB);
    cudaFuncSetAttribute(k_ffn,    cudaFuncAttributeMaxDynamicSharedMemorySize, SM_F);

    k_prep<<<(W_TOT + 255) / 256, 256>>>(e_w, wq, wk, wv, wq_src, afc_w, f_w1, f_w2);
    k_zqkv<<<gM, NT, SM_ZQKV>>>(nh, t, t_now, ef, bfreq, phase, e_b, totrows);
    k_selfq<<<(N + 63) / 64, NT, SM_AB>>>(N);
    k_attn<<<(N + 2) / 3, NT, SM_ATT>>>(N);
    k_attnfc<<<gM, NT, SM_AB>>>(afc_b, aln_g, aln_b, totrows);
    k_ffn<<<(N + 2) / 3, NT, SM_F>>>(f_b1, f_b2, fln_g, fln_b,
                                     f2n_w, f2n_b, oln_g, oln_b, nh, out, N);
}